// round 7
// baseline (speedup 1.0000x reference)
#include <cuda_runtime.h>
#include <cstdint>

// ---------------------------------------------------------------------------
// SimpleGNNDenoiser: 5-layer GCN, N=100k, E=3.2M.
//   Â(XW) = (ÂX)W  -> aggregate at min(din,dout) per layer.
// R7: every dense layer fused into a gather epilogue (smem row staging +
//     smem-resident weights); h3 never materialized (dense3·dense4 chained
//     in K3's epilogue). 9 launches total.
// ---------------------------------------------------------------------------

#define N_MAX 100000
#define E_MAX 3200000
#define SCAN_B 1024

static __device__ float g_bufA[N_MAX * 64];
static __device__ float g_bufB[N_MAX * 64];
static __device__ float4 g_pack[N_MAX];              // [cx,cy,cz, type-bits]
static __device__ float g_dinv[N_MAX];
static __device__ int2  g_csr[E_MAX];
static __device__ int   g_rp[N_MAX + 1];
static __device__ int   g_cnt[N_MAX];
static __device__ int   g_cur[N_MAX];
static __device__ unsigned long long g_state[128];   // lookback: (status<<32)|sum

// ---- CSR build ---------------------------------------------------------------

__global__ void k_hist(const int* __restrict__ dst, int* cnt, int E) {
    int e = blockIdx.x * blockDim.x + threadIdx.x;
    if (e < E) atomicAdd(&cnt[dst[e]], 1);
}

// Single-pass decoupled-lookback exclusive scan; also emits dinv and the
// packed [coords|type] float4 per node. 98 blocks co-resident -> no deadlock.
__global__ void __launch_bounds__(SCAN_B)
k_scan_lb(const int* __restrict__ cnt, unsigned long long* __restrict__ state,
          int* __restrict__ rp, int* __restrict__ cur, float* __restrict__ dinv,
          const float* __restrict__ coords, const int* __restrict__ types,
          float4* __restrict__ pack, int n) {
    __shared__ int s[SCAN_B];
    __shared__ int sbase;
    int t = threadIdx.x;
    int bid = blockIdx.x;
    int i = bid * SCAN_B + t;
    int v = (i < n) ? cnt[i] : 0;
    s[t] = v;
    __syncthreads();
    for (int off = 1; off < SCAN_B; off <<= 1) {
        int u = (t >= off) ? s[t - off] : 0;
        __syncthreads();
        s[t] += u;
        __syncthreads();
    }
    int total = s[SCAN_B - 1];

    if (t == 0) {
        if (bid == 0) {
            atomicExch(&state[0], (2ULL << 32) | (unsigned)total);
            sbase = 0;
        } else {
            atomicExch(&state[bid], (1ULL << 32) | (unsigned)total);
            int run = 0;
            int p = bid - 1;
            while (p >= 0) {
                unsigned long long w;
                do { w = atomicAdd(&state[p], 0ULL); } while ((w >> 32) == 0ULL);
                run += (int)(w & 0xffffffffULL);
                if ((w >> 32) == 2ULL) break;
                p--;
            }
            atomicExch(&state[bid], (2ULL << 32) | (unsigned)(run + total));
            sbase = run;
        }
    }
    __syncthreads();
    if (i < n) {
        int excl = sbase + s[t] - v;
        rp[i] = excl;
        cur[i] = excl;
        dinv[i] = rsqrtf(1.0f + (float)v);
        if (i == n - 1) rp[n] = excl + v;
        float4 p;
        p.x = coords[3 * (size_t)i + 0];
        p.y = coords[3 * (size_t)i + 1];
        p.z = coords[3 * (size_t)i + 2];
        p.w = __int_as_float(types[i]);
        pack[i] = p;
    }
}

__global__ void k_fill(const int* __restrict__ src, const int* __restrict__ dst,
                       const float* __restrict__ dinv, int* __restrict__ cur,
                       int2* __restrict__ csr, int E) {
    int e = blockIdx.x * blockDim.x + threadIdx.x;
    if (e >= E) return;
    int s = src[e], d = dst[e];
    int pos = atomicAdd(&cur[d], 1);
    float nm = dinv[s] * dinv[d];
    csr[pos] = make_int2(s, __float_as_int(nm));
}

// ---- shared gather core: warp computes Â x row i (incl. self loop) into smem -
// U independent load streams; result (W floats) parked in `row` by SL lanes.

template<int W, int U>
__device__ __forceinline__ void gather_row(
    const int2* __restrict__ csr, const int* __restrict__ rp,
    const float* __restrict__ x, const float* __restrict__ dinv,
    int i, int lane, float* row) {
    constexpr int SL = W / 4;
    constexpr int NB = 32 / SL;
    int nb = lane / SL;
    int c4 = lane & (SL - 1);
    int beg = rp[i], end = rp[i + 1];

    const float4* x4 = reinterpret_cast<const float4*>(x);

    float4 a[U];
    int idx[U];
    int2 e[U];
#pragma unroll
    for (int u = 0; u < U; u++) {
        a[u] = make_float4(0.f, 0.f, 0.f, 0.f);
        idx[u] = beg + nb + u * NB;
        if (idx[u] < end) e[u] = csr[idx[u]];
        else { e[u].x = i; e[u].y = 0; }
    }

    for (int j = beg; j < end; j += U * NB) {
        int2 c[U];
#pragma unroll
        for (int u = 0; u < U; u++) {
            c[u] = e[u];
            idx[u] += U * NB;
            if (idx[u] < end) e[u] = csr[idx[u]];
            else { e[u].x = i; e[u].y = 0; }
        }
#pragma unroll
        for (int u = 0; u < U; u++) {
            float w = __int_as_float(c[u].y);
            float4 v = x4[(size_t)c[u].x * SL + c4];
            a[u].x = fmaf(v.x, w, a[u].x);
            a[u].y = fmaf(v.y, w, a[u].y);
            a[u].z = fmaf(v.z, w, a[u].z);
            a[u].w = fmaf(v.w, w, a[u].w);
        }
    }

    float4 acc = a[0];
#pragma unroll
    for (int u = 1; u < U; u++) {
        acc.x += a[u].x; acc.y += a[u].y; acc.z += a[u].z; acc.w += a[u].w;
    }
#pragma unroll
    for (int off = SL; off < 32; off <<= 1) {
        acc.x += __shfl_xor_sync(0xffffffffu, acc.x, off);
        acc.y += __shfl_xor_sync(0xffffffffu, acc.y, off);
        acc.z += __shfl_xor_sync(0xffffffffu, acc.z, off);
        acc.w += __shfl_xor_sync(0xffffffffu, acc.w, off);
    }
    if (lane < SL) {
        float dv = dinv[i];
        float dv2 = dv * dv;
        float4 xs = x4[(size_t)i * SL + c4];
        acc.x = fmaf(xs.x, dv2, acc.x);
        acc.y = fmaf(xs.y, dv2, acc.y);
        acc.z = fmaf(xs.z, dv2, acc.z);
        acc.w = fmaf(xs.w, dv2, acc.w);
        reinterpret_cast<float4*>(row)[c4] = acc;
    }
}

// ---- K1: fused packed gather + dense1(6->32) + bias + relu -------------------

__global__ void __launch_bounds__(256)
k_l1_fused(const int2* __restrict__ csr, const int* __restrict__ rp,
           const float4* __restrict__ pack, const float* __restrict__ emb,
           const float* __restrict__ dinv, const float* __restrict__ W1,
           const float* __restrict__ b1, float* __restrict__ out, int n) {
    int warp = (blockIdx.x * blockDim.x + threadIdx.x) >> 5;
    if (warp >= n) return;
    int lane = threadIdx.x & 31;
    int i = warp;
    int beg = rp[i], end = rp[i + 1];

    float ax = 0.f, ay = 0.f, az = 0.f, m0 = 0.f, m1 = 0.f;
    for (int idx = beg + lane; idx < end; idx += 32) {
        int2 e = csr[idx];
        float w = __int_as_float(e.y);
        float4 p = pack[e.x];
        ax = fmaf(p.x, w, ax);
        ay = fmaf(p.y, w, ay);
        az = fmaf(p.z, w, az);
        if (__float_as_int(p.w) == 0) m0 += w; else m1 += w;
    }
#pragma unroll
    for (int off = 1; off < 32; off <<= 1) {
        ax += __shfl_xor_sync(0xffffffffu, ax, off);
        ay += __shfl_xor_sync(0xffffffffu, ay, off);
        az += __shfl_xor_sync(0xffffffffu, az, off);
        m0 += __shfl_xor_sync(0xffffffffu, m0, off);
        m1 += __shfl_xor_sync(0xffffffffu, m1, off);
    }
    float dv = dinv[i];
    float dv2 = dv * dv;
    float4 ps = pack[i];
    ax = fmaf(ps.x, dv2, ax);
    ay = fmaf(ps.y, dv2, ay);
    az = fmaf(ps.z, dv2, az);
    if (__float_as_int(ps.w) == 0) m0 += dv2; else m1 += dv2;

    float x3 = fmaf(m0, emb[0], m1 * emb[3]);
    float x4 = fmaf(m0, emb[1], m1 * emb[4]);
    float x5 = fmaf(m0, emb[2], m1 * emb[5]);

    float acc = b1[lane];
    acc = fmaf(ax, W1[0 * 32 + lane], acc);
    acc = fmaf(ay, W1[1 * 32 + lane], acc);
    acc = fmaf(az, W1[2 * 32 + lane], acc);
    acc = fmaf(x3, W1[3 * 32 + lane], acc);
    acc = fmaf(x4, W1[4 * 32 + lane], acc);
    acc = fmaf(x5, W1[5 * 32 + lane], acc);
    out[(size_t)i * 32 + lane] = fmaxf(acc, 0.f);
}

// ---- K2: gather@32 + dense 32->64 (+b2, relu) -------------------------------

__global__ void __launch_bounds__(512)
k_l2(const int2* __restrict__ csr, const int* __restrict__ rp,
     const float* __restrict__ x, const float* __restrict__ dinv,
     const float* __restrict__ W2, const float* __restrict__ b2,
     float* __restrict__ out, int n) {
    __shared__ float Ws[32 * 64];
    __shared__ float bs[64];
    __shared__ float rows[16][32];
    for (int t = threadIdx.x; t < 32 * 64; t += 512) Ws[t] = W2[t];
    for (int t = threadIdx.x; t < 64; t += 512) bs[t] = b2[t];
    __syncthreads();

    int warp = (blockIdx.x * blockDim.x + threadIdx.x) >> 5;
    if (warp >= n) return;
    int lane = threadIdx.x & 31;
    int wid = (threadIdx.x >> 5);
    float* row = rows[wid];

    gather_row<32, 4>(csr, rp, x, dinv, warp, lane, row);
    __syncwarp();

    float acc0 = bs[lane], acc1 = bs[lane + 32];
    const float4* r4 = reinterpret_cast<const float4*>(row);
#pragma unroll
    for (int k4 = 0; k4 < 8; k4++) {
        float4 xv = r4[k4];
        int k = k4 * 4;
        acc0 = fmaf(xv.x, Ws[(k + 0) * 64 + lane], acc0);
        acc1 = fmaf(xv.x, Ws[(k + 0) * 64 + lane + 32], acc1);
        acc0 = fmaf(xv.y, Ws[(k + 1) * 64 + lane], acc0);
        acc1 = fmaf(xv.y, Ws[(k + 1) * 64 + lane + 32], acc1);
        acc0 = fmaf(xv.z, Ws[(k + 2) * 64 + lane], acc0);
        acc1 = fmaf(xv.z, Ws[(k + 2) * 64 + lane + 32], acc1);
        acc0 = fmaf(xv.w, Ws[(k + 3) * 64 + lane], acc0);
        acc1 = fmaf(xv.w, Ws[(k + 3) * 64 + lane + 32], acc1);
    }
    out[(size_t)warp * 64 + lane] = fmaxf(acc0, 0.f);
    out[(size_t)warp * 64 + 32 + lane] = fmaxf(acc1, 0.f);
}

// ---- K3: gather@64 + dense 64->64 (+b3, relu) + dense 64->32 ----------------
// h3 is never written to global; t4 = relu(y W3 + b3) W4 goes straight out.

__global__ void __launch_bounds__(512)
k_l3(const int2* __restrict__ csr, const int* __restrict__ rp,
     const float* __restrict__ x, const float* __restrict__ dinv,
     const float* __restrict__ W3, const float* __restrict__ b3,
     const float* __restrict__ W4, float* __restrict__ out, int n) {
    __shared__ float W3s[64 * 64];
    __shared__ float W4s[64 * 32];
    __shared__ float bs[64];
    __shared__ float rows[16][64];
    for (int t = threadIdx.x; t < 64 * 64; t += 512) W3s[t] = W3[t];
    for (int t = threadIdx.x; t < 64 * 32; t += 512) W4s[t] = W4[t];
    for (int t = threadIdx.x; t < 64; t += 512) bs[t] = b3[t];
    __syncthreads();

    int warp = (blockIdx.x * blockDim.x + threadIdx.x) >> 5;
    if (warp >= n) return;
    int lane = threadIdx.x & 31;
    int wid = (threadIdx.x >> 5);
    float* row = rows[wid];

    gather_row<64, 4>(csr, rp, x, dinv, warp, lane, row);
    __syncwarp();

    // dense3: two columns per lane
    float acc0 = bs[lane], acc1 = bs[lane + 32];
    const float4* r4 = reinterpret_cast<const float4*>(row);
#pragma unroll
    for (int k4 = 0; k4 < 16; k4++) {
        float4 xv = r4[k4];
        int k = k4 * 4;
        acc0 = fmaf(xv.x, W3s[(k + 0) * 64 + lane], acc0);
        acc1 = fmaf(xv.x, W3s[(k + 0) * 64 + lane + 32], acc1);
        acc0 = fmaf(xv.y, W3s[(k + 1) * 64 + lane], acc0);
        acc1 = fmaf(xv.y, W3s[(k + 1) * 64 + lane + 32], acc1);
        acc0 = fmaf(xv.z, W3s[(k + 2) * 64 + lane], acc0);
        acc1 = fmaf(xv.z, W3s[(k + 2) * 64 + lane + 32], acc1);
        acc0 = fmaf(xv.w, W3s[(k + 3) * 64 + lane], acc0);
        acc1 = fmaf(xv.w, W3s[(k + 3) * 64 + lane + 32], acc1);
    }
    __syncwarp();                      // row reads done before overwrite
    row[lane] = fmaxf(acc0, 0.f);
    row[lane + 32] = fmaxf(acc1, 0.f);
    __syncwarp();

    // dense4: one column per lane, no bias (b4 folded into K5)
    float acc = 0.f;
#pragma unroll
    for (int k4 = 0; k4 < 16; k4++) {
        float4 xv = r4[k4];
        int k = k4 * 4;
        acc = fmaf(xv.x, W4s[(k + 0) * 32 + lane], acc);
        acc = fmaf(xv.y, W4s[(k + 1) * 32 + lane], acc);
        acc = fmaf(xv.z, W4s[(k + 2) * 32 + lane], acc);
        acc = fmaf(xv.w, W4s[(k + 3) * 32 + lane], acc);
    }
    out[(size_t)warp * 32 + lane] = acc;
}

// ---- K5: gather@32 (+b4, relu) + dense 32->3 -> t5 (stride 4, padded) -------

__global__ void __launch_bounds__(512)
k_l5(const int2* __restrict__ csr, const int* __restrict__ rp,
     const float* __restrict__ x, const float* __restrict__ dinv,
     const float* __restrict__ b4, const float* __restrict__ W5,
     float* __restrict__ out, int n) {
    __shared__ float W5s[32 * 3];
    __shared__ float bs[32];
    __shared__ float rows[16][32];
    for (int t = threadIdx.x; t < 96; t += 512) W5s[t] = W5[t];
    for (int t = threadIdx.x; t < 32; t += 512) bs[t] = b4[t];
    __syncthreads();

    int warp = (blockIdx.x * blockDim.x + threadIdx.x) >> 5;
    if (warp >= n) return;
    int lane = threadIdx.x & 31;
    int wid = (threadIdx.x >> 5);
    float* row = rows[wid];

    gather_row<32, 4>(csr, rp, x, dinv, warp, lane, row);
    __syncwarp();

    float h = fmaxf(row[lane] + bs[lane], 0.f);   // h4 element `lane`
    __syncwarp();
    row[lane] = h;
    __syncwarp();

    if (lane < 4) {
        float acc = 0.f;
        if (lane < 3) {
#pragma unroll
            for (int k = 0; k < 32; k++) acc = fmaf(row[k], W5s[k * 3 + lane], acc);
        }
        out[(size_t)warp * 4 + lane] = acc;       // lane 3 writes pad 0
    }
}

// ---- K6: gather@4 (+b5) -> d_out (width 3) ----------------------------------

__global__ void __launch_bounds__(256)
k_l6(const int2* __restrict__ csr, const int* __restrict__ rp,
     const float* __restrict__ x, const float* __restrict__ dinv,
     const float* __restrict__ b5, float* __restrict__ y, int n) {
    int warp = (blockIdx.x * blockDim.x + threadIdx.x) >> 5;
    if (warp >= n) return;
    int lane = threadIdx.x & 31;
    int i = warp;
    int beg = rp[i], end = rp[i + 1];
    const float4* x4 = reinterpret_cast<const float4*>(x);

    float4 a0 = make_float4(0.f, 0.f, 0.f, 0.f);
    float4 a1 = make_float4(0.f, 0.f, 0.f, 0.f);
    int idx0 = beg + lane;
    int idx1 = idx0 + 32;
    int2 e0, e1;
    if (idx0 < end) e0 = csr[idx0]; else { e0.x = i; e0.y = 0; }
    if (idx1 < end) e1 = csr[idx1]; else { e1.x = i; e1.y = 0; }
    for (int j = beg; j < end; j += 64) {
        int2 c0 = e0, c1 = e1;
        idx0 += 64; idx1 += 64;
        if (idx0 < end) e0 = csr[idx0]; else { e0.x = i; e0.y = 0; }
        if (idx1 < end) e1 = csr[idx1]; else { e1.x = i; e1.y = 0; }
        float w0 = __int_as_float(c0.y);
        float w1 = __int_as_float(c1.y);
        float4 v0 = x4[c0.x];
        float4 v1 = x4[c1.x];
        a0.x = fmaf(v0.x, w0, a0.x); a0.y = fmaf(v0.y, w0, a0.y); a0.z = fmaf(v0.z, w0, a0.z);
        a1.x = fmaf(v1.x, w1, a1.x); a1.y = fmaf(v1.y, w1, a1.y); a1.z = fmaf(v1.z, w1, a1.z);
    }
    float rx = a0.x + a1.x, ry = a0.y + a1.y, rz = a0.z + a1.z;
#pragma unroll
    for (int off = 1; off < 32; off <<= 1) {
        rx += __shfl_xor_sync(0xffffffffu, rx, off);
        ry += __shfl_xor_sync(0xffffffffu, ry, off);
        rz += __shfl_xor_sync(0xffffffffu, rz, off);
    }
    if (lane == 0) {
        float dv = dinv[i];
        float dv2 = dv * dv;
        float4 xs = x4[i];
        float* yr = y + (size_t)i * 3;
        yr[0] = fmaf(xs.x, dv2, rx) + b5[0];
        yr[1] = fmaf(xs.y, dv2, ry) + b5[1];
        yr[2] = fmaf(xs.z, dv2, rz) + b5[2];
    }
}

// ---------------------------------------------------------------------------

static inline int blocks_for(long long work, int tpb) {
    return (int)((work + tpb - 1) / tpb);
}

extern "C" void kernel_launch(void* const* d_in, const int* in_sizes, int n_in,
                              void* d_out, int out_size) {
    const float* coords = (const float*)d_in[0];
    const int*   types  = (const int*)d_in[1];
    const int*   edge   = (const int*)d_in[2];
    const float* emb    = (const float*)d_in[3];
    const float* W1 = (const float*)d_in[4];
    const float* b1 = (const float*)d_in[5];
    const float* W2 = (const float*)d_in[6];
    const float* b2 = (const float*)d_in[7];
    const float* W3 = (const float*)d_in[8];
    const float* b3 = (const float*)d_in[9];
    const float* W4 = (const float*)d_in[10];
    const float* b4 = (const float*)d_in[11];
    const float* W5 = (const float*)d_in[12];
    const float* b5 = (const float*)d_in[13];
    float* out = (float*)d_out;

    const int n = in_sizes[0] / 3;
    const int E = in_sizes[2] / 2;
    const int* src = edge;
    const int* dst = edge + E;

    float *A, *B, *dinv;
    float4* pack;
    int2* csr;
    int *rp, *cnt, *cur;
    unsigned long long* state;
    cudaGetSymbolAddress((void**)&A, g_bufA);
    cudaGetSymbolAddress((void**)&B, g_bufB);
    cudaGetSymbolAddress((void**)&pack, g_pack);
    cudaGetSymbolAddress((void**)&dinv, g_dinv);
    cudaGetSymbolAddress((void**)&csr, g_csr);
    cudaGetSymbolAddress((void**)&rp, g_rp);
    cudaGetSymbolAddress((void**)&cnt, g_cnt);
    cudaGetSymbolAddress((void**)&cur, g_cur);
    cudaGetSymbolAddress((void**)&state, g_state);

    const int T = 256;
    const long long nw = (long long)n * 32;   // one warp per node
    const int PB = blocks_for(n, SCAN_B);     // 98 scan blocks

    cudaMemsetAsync(cnt, 0, (size_t)n * sizeof(int));
    cudaMemsetAsync(state, 0, 128 * sizeof(unsigned long long));

    // ---- CSR build + packed features ----
    k_hist<<<blocks_for(E, T), T>>>(dst, cnt, E);                                 // 1
    k_scan_lb<<<PB, SCAN_B>>>(cnt, state, rp, cur, dinv, coords, types, pack, n); // 2
    k_fill<<<blocks_for(E, T), T>>>(src, dst, dinv, cur, csr, E);                 // 3

    // K1: L1 fused -> h1 in A (stride 32)                   [launch 4: profiled]
    k_l1_fused<<<blocks_for(nw, T), T>>>(csr, rp, pack, emb, dinv, W1, b1, A, n);

    // K2: gather@32(h1) + dense2 -> h2 in B (64)
    k_l2<<<blocks_for(nw, 512), 512>>>(csr, rp, A, dinv, W2, b2, B, n);

    // K3: gather@64(h2) + dense3 + relu + dense4 -> t4 in A (32)
    k_l3<<<blocks_for(nw, 512), 512>>>(csr, rp, B, dinv, W3, b3, W4, A, n);

    // K5: gather@32(t4) + b4 + relu + dense5 -> t5 in B (stride 4)
    k_l5<<<blocks_for(nw, 512), 512>>>(csr, rp, A, dinv, b4, W5, B, n);

    // K6: gather@4(t5) + b5 -> out (width 3)
    k_l6<<<blocks_for(nw, T), T>>>(csr, rp, B, dinv, b5, out, n);
}

// round 8
// speedup vs baseline: 1.0849x; 1.0849x over previous
#include <cuda_runtime.h>
#include <cstdint>

// ---------------------------------------------------------------------------
// SimpleGNNDenoiser: 5-layer GCN, N=100k, E=3.2M.
//   Â(XW) = (ÂX)W  -> aggregate at min(din,dout) per layer.
// R8: revert R7 fusion (regressed). "z-trick": producers store z = dinv*h,
//     so aggregation needs NO per-edge norm: y_i = dinv_i*(sum z_s + z_i).
//     CSR entry is a bare int src (halved), fill has no scattered dinv loads,
//     L1 pack = [dinv*c, +-dinv] with type in the sign bit.
// ---------------------------------------------------------------------------

#define N_MAX 100000
#define E_MAX 3200000
#define SCAN_B 1024

static __device__ float g_bufA[N_MAX * 64];
static __device__ float g_bufB[N_MAX * 64];
static __device__ float4 g_pack[N_MAX];              // [dinv*cx, dinv*cy, dinv*cz, +-dinv]
static __device__ float g_dinv[N_MAX];
static __device__ int   g_csr[E_MAX];
static __device__ int   g_rp[N_MAX + 1];
static __device__ int   g_cnt[N_MAX];
static __device__ int   g_cur[N_MAX];
static __device__ unsigned long long g_state[128];   // lookback: (status<<32)|sum

// ---- CSR build ---------------------------------------------------------------

__global__ void k_hist(const int* __restrict__ dst, int* cnt, int E) {
    int e = blockIdx.x * blockDim.x + threadIdx.x;
    if (e < E) atomicAdd(&cnt[dst[e]], 1);
}

// Single-pass decoupled-lookback exclusive scan; emits rp, cur, dinv and the
// dinv-scaled packed features. 98 blocks co-resident -> lookback can't deadlock.
__global__ void __launch_bounds__(SCAN_B)
k_scan_lb(const int* __restrict__ cnt, unsigned long long* __restrict__ state,
          int* __restrict__ rp, int* __restrict__ cur, float* __restrict__ dinv,
          const float* __restrict__ coords, const int* __restrict__ types,
          float4* __restrict__ pack, int n) {
    __shared__ int s[SCAN_B];
    __shared__ int sbase;
    int t = threadIdx.x;
    int bid = blockIdx.x;
    int i = bid * SCAN_B + t;
    int v = (i < n) ? cnt[i] : 0;
    s[t] = v;
    __syncthreads();
    for (int off = 1; off < SCAN_B; off <<= 1) {
        int u = (t >= off) ? s[t - off] : 0;
        __syncthreads();
        s[t] += u;
        __syncthreads();
    }
    int total = s[SCAN_B - 1];

    if (t == 0) {
        if (bid == 0) {
            atomicExch(&state[0], (2ULL << 32) | (unsigned)total);
            sbase = 0;
        } else {
            atomicExch(&state[bid], (1ULL << 32) | (unsigned)total);
            int run = 0;
            int p = bid - 1;
            while (p >= 0) {
                unsigned long long w;
                do { w = atomicAdd(&state[p], 0ULL); } while ((w >> 32) == 0ULL);
                run += (int)(w & 0xffffffffULL);
                if ((w >> 32) == 2ULL) break;
                p--;
            }
            atomicExch(&state[bid], (2ULL << 32) | (unsigned)(run + total));
            sbase = run;
        }
    }
    __syncthreads();
    if (i < n) {
        int excl = sbase + s[t] - v;
        rp[i] = excl;
        cur[i] = excl;
        float dv = rsqrtf(1.0f + (float)v);
        dinv[i] = dv;
        if (i == n - 1) rp[n] = excl + v;
        float4 p;
        p.x = dv * coords[3 * (size_t)i + 0];
        p.y = dv * coords[3 * (size_t)i + 1];
        p.z = dv * coords[3 * (size_t)i + 2];
        p.w = (types[i] == 0) ? dv : -dv;
        pack[i] = p;
    }
}

__global__ void k_fill(const int* __restrict__ src, const int* __restrict__ dst,
                       int* __restrict__ cur, int* __restrict__ csr, int E) {
    int e = blockIdx.x * blockDim.x + threadIdx.x;
    if (e >= E) return;
    int d = dst[e];
    int pos = atomicAdd(&cur[d], 1);
    csr[pos] = src[e];
}

// ---- K1: fused packed gather + dense1(6->32) + bias + relu; writes z1 --------
// pack rows are pre-scaled by dinv_s; type mass from sign of pack.w.

__global__ void __launch_bounds__(256)
k_l1_fused(const int* __restrict__ csr, const int* __restrict__ rp,
           const float4* __restrict__ pack, const float* __restrict__ emb,
           const float* __restrict__ dinv, const float* __restrict__ W1,
           const float* __restrict__ b1, float* __restrict__ out, int n) {
    int warp = (blockIdx.x * blockDim.x + threadIdx.x) >> 5;
    if (warp >= n) return;
    int lane = threadIdx.x & 31;
    int i = warp;
    int beg = rp[i], end = rp[i + 1];

    float ax = 0.f, ay = 0.f, az = 0.f, m0 = 0.f, m1 = 0.f;
    for (int idx = beg + lane; idx < end; idx += 32) {
        float4 p = pack[csr[idx]];
        ax += p.x; ay += p.y; az += p.z;
        m0 += fmaxf(p.w, 0.f);
        m1 += fmaxf(-p.w, 0.f);
    }
#pragma unroll
    for (int off = 1; off < 32; off <<= 1) {
        ax += __shfl_xor_sync(0xffffffffu, ax, off);
        ay += __shfl_xor_sync(0xffffffffu, ay, off);
        az += __shfl_xor_sync(0xffffffffu, az, off);
        m0 += __shfl_xor_sync(0xffffffffu, m0, off);
        m1 += __shfl_xor_sync(0xffffffffu, m1, off);
    }
    float dv = dinv[i];
    float4 ps = pack[i];                 // self term (z row)
    ax = dv * (ax + ps.x);
    ay = dv * (ay + ps.y);
    az = dv * (az + ps.z);
    m0 = dv * (m0 + fmaxf(ps.w, 0.f));
    m1 = dv * (m1 + fmaxf(-ps.w, 0.f));

    float x3 = fmaf(m0, emb[0], m1 * emb[3]);
    float x4 = fmaf(m0, emb[1], m1 * emb[4]);
    float x5 = fmaf(m0, emb[2], m1 * emb[5]);

    float acc = b1[lane];
    acc = fmaf(ax, W1[0 * 32 + lane], acc);
    acc = fmaf(ay, W1[1 * 32 + lane], acc);
    acc = fmaf(az, W1[2 * 32 + lane], acc);
    acc = fmaf(x3, W1[3 * 32 + lane], acc);
    acc = fmaf(x4, W1[4 * 32 + lane], acc);
    acc = fmaf(x5, W1[5 * 32 + lane], acc);
    out[(size_t)i * 32 + lane] = dv * fmaxf(acc, 0.f);   // z1 = dinv * h1
}

// ---- warp-per-node CSR gather, U-way streams; y = dinv_i*(sum z + z_i) ------
// Optional +bias and relu (for the L4 aggregation whose output feeds dense5).

template<int W, int OUTW, int U, bool BIAS, bool RELU>
__global__ void __launch_bounds__(256)
k_gather(const int* __restrict__ csr, const int* __restrict__ rp,
         const float* __restrict__ x, const float* __restrict__ dinv,
         const float* __restrict__ b, float* __restrict__ y, int n) {
    constexpr int SL = W / 4;
    constexpr int NB = 32 / SL;
    int warp = (blockIdx.x * blockDim.x + threadIdx.x) >> 5;
    if (warp >= n) return;
    int lane = threadIdx.x & 31;
    int nb = lane / SL;
    int c4 = lane & (SL - 1);
    int i = warp;
    int beg = rp[i], end = rp[i + 1];

    const float4* x4 = reinterpret_cast<const float4*>(x);

    float4 a[U];
    int idx[U];
    int s[U];
    float wv[U];
#pragma unroll
    for (int u = 0; u < U; u++) {
        a[u] = make_float4(0.f, 0.f, 0.f, 0.f);
        idx[u] = beg + nb + u * NB;
        if (idx[u] < end) { s[u] = csr[idx[u]]; wv[u] = 1.f; }
        else { s[u] = i; wv[u] = 0.f; }
    }

    for (int j = beg; j < end; j += U * NB) {
        int cs[U];
        float cw[U];
#pragma unroll
        for (int u = 0; u < U; u++) {
            cs[u] = s[u]; cw[u] = wv[u];
            idx[u] += U * NB;
            if (idx[u] < end) { s[u] = csr[idx[u]]; wv[u] = 1.f; }
            else { s[u] = i; wv[u] = 0.f; }
        }
#pragma unroll
        for (int u = 0; u < U; u++) {
            float4 v = x4[(size_t)cs[u] * SL + c4];
            a[u].x = fmaf(v.x, cw[u], a[u].x);
            a[u].y = fmaf(v.y, cw[u], a[u].y);
            a[u].z = fmaf(v.z, cw[u], a[u].z);
            a[u].w = fmaf(v.w, cw[u], a[u].w);
        }
    }

    float4 acc = a[0];
#pragma unroll
    for (int u = 1; u < U; u++) {
        acc.x += a[u].x; acc.y += a[u].y; acc.z += a[u].z; acc.w += a[u].w;
    }
#pragma unroll
    for (int off = SL; off < 32; off <<= 1) {
        acc.x += __shfl_xor_sync(0xffffffffu, acc.x, off);
        acc.y += __shfl_xor_sync(0xffffffffu, acc.y, off);
        acc.z += __shfl_xor_sync(0xffffffffu, acc.z, off);
        acc.w += __shfl_xor_sync(0xffffffffu, acc.w, off);
    }

    if (lane < SL) {
        float dv = dinv[i];
        float4 xs = x4[(size_t)i * SL + c4];     // self z row
        float4 r;
        r.x = dv * (acc.x + xs.x);
        r.y = dv * (acc.y + xs.y);
        r.z = dv * (acc.z + xs.z);
        r.w = dv * (acc.w + xs.w);
        int col = c4 * 4;
        if (BIAS) {
            if (col + 0 < OUTW) r.x += b[col + 0];
            if (col + 1 < OUTW) r.y += b[col + 1];
            if (col + 2 < OUTW) r.z += b[col + 2];
            if (col + 3 < OUTW) r.w += b[col + 3];
        }
        if (RELU) {
            r.x = fmaxf(r.x, 0.f); r.y = fmaxf(r.y, 0.f);
            r.z = fmaxf(r.z, 0.f); r.w = fmaxf(r.w, 0.f);
        }
        if constexpr (OUTW % 4 == 0) {
            reinterpret_cast<float4*>(y + (size_t)i * OUTW)[c4] = r;
        } else {                    // OUTW==3 (final layer), SL==1
            float* yr = y + (size_t)i * OUTW;
            yr[0] = r.x; yr[1] = r.y; yr[2] = r.z;
        }
    }
}

// ---- dense transform: out = scale? dinv* : 1 * act(x @ W + b) ---------------

template<int DIN, int DOUT, int INS, int OUTS, bool BIAS, bool RELU, bool SCALE>
__global__ void __launch_bounds__(128)
k_dense(const float* __restrict__ x, const float* __restrict__ Wm,
        const float* __restrict__ b, const float* __restrict__ dinv,
        float* __restrict__ out, int n) {
    __shared__ float Ws[DIN * DOUT];
    __shared__ float bs[DOUT];
    for (int t = threadIdx.x; t < DIN * DOUT; t += blockDim.x) Ws[t] = Wm[t];
    for (int t = threadIdx.x; t < DOUT; t += blockDim.x) bs[t] = BIAS ? b[t] : 0.0f;
    __syncthreads();
    int i = blockIdx.x * blockDim.x + threadIdx.x;
    if (i >= n) return;
    float acc[DOUT];
#pragma unroll
    for (int j = 0; j < DOUT; j++) acc[j] = bs[j];

    const float4* x4 = reinterpret_cast<const float4*>(x + (size_t)i * INS);
#pragma unroll
    for (int k4 = 0; k4 < DIN / 4; k4++) {
        float4 xv = x4[k4];
        int k = k4 * 4;
#pragma unroll
        for (int j = 0; j < DOUT; j++) {
            acc[j] = fmaf(xv.x, Ws[(k + 0) * DOUT + j], acc[j]);
            acc[j] = fmaf(xv.y, Ws[(k + 1) * DOUT + j], acc[j]);
            acc[j] = fmaf(xv.z, Ws[(k + 2) * DOUT + j], acc[j]);
            acc[j] = fmaf(xv.w, Ws[(k + 3) * DOUT + j], acc[j]);
        }
    }
    float sc = SCALE ? dinv[i] : 1.0f;
    float* o = out + (size_t)i * OUTS;
#pragma unroll
    for (int j = 0; j < DOUT; j++) {
        float v = RELU ? fmaxf(acc[j], 0.0f) : acc[j];
        o[j] = sc * v;
    }
#pragma unroll
    for (int j = DOUT; j < OUTS; j++) o[j] = 0.0f;
}

// ---------------------------------------------------------------------------

static inline int blocks_for(long long work, int tpb) {
    return (int)((work + tpb - 1) / tpb);
}

extern "C" void kernel_launch(void* const* d_in, const int* in_sizes, int n_in,
                              void* d_out, int out_size) {
    const float* coords = (const float*)d_in[0];
    const int*   types  = (const int*)d_in[1];
    const int*   edge   = (const int*)d_in[2];
    const float* emb    = (const float*)d_in[3];
    const float* W1 = (const float*)d_in[4];
    const float* b1 = (const float*)d_in[5];
    const float* W2 = (const float*)d_in[6];
    const float* b2 = (const float*)d_in[7];
    const float* W3 = (const float*)d_in[8];
    const float* b3 = (const float*)d_in[9];
    const float* W4 = (const float*)d_in[10];
    const float* b4 = (const float*)d_in[11];
    const float* W5 = (const float*)d_in[12];
    const float* b5 = (const float*)d_in[13];
    float* out = (float*)d_out;

    const int n = in_sizes[0] / 3;
    const int E = in_sizes[2] / 2;
    const int* src = edge;
    const int* dst = edge + E;

    float *A, *B, *dinv;
    float4* pack;
    int *csr, *rp, *cnt, *cur;
    unsigned long long* state;
    cudaGetSymbolAddress((void**)&A, g_bufA);
    cudaGetSymbolAddress((void**)&B, g_bufB);
    cudaGetSymbolAddress((void**)&pack, g_pack);
    cudaGetSymbolAddress((void**)&dinv, g_dinv);
    cudaGetSymbolAddress((void**)&csr, g_csr);
    cudaGetSymbolAddress((void**)&rp, g_rp);
    cudaGetSymbolAddress((void**)&cnt, g_cnt);
    cudaGetSymbolAddress((void**)&cur, g_cur);
    cudaGetSymbolAddress((void**)&state, g_state);

    const int T = 256;
    const long long nw = (long long)n * 32;   // one warp per node
    const int PB = blocks_for(n, SCAN_B);     // 98 scan blocks

    cudaMemsetAsync(cnt, 0, (size_t)n * sizeof(int));
    cudaMemsetAsync(state, 0, 128 * sizeof(unsigned long long));

    // ---- CSR build + packed z-features ----
    k_hist<<<blocks_for(E, T), T>>>(dst, cnt, E);                                 // 1
    k_scan_lb<<<PB, SCAN_B>>>(cnt, state, rp, cur, dinv, coords, types, pack, n); // 2
    k_fill<<<blocks_for(E, T), T>>>(src, dst, cur, csr, E);                       // 3

    // K1: L1 fused -> z1 in A (stride 32)                   [launch 4: profiled]
    k_l1_fused<<<blocks_for(nw, T), T>>>(csr, rp, pack, emb, dinv, W1, b1, A, n);

    // L2: y2 = agg(z1) -> B ; z2 = dinv*relu(y2 W2 + b2) -> A (64)
    k_gather<32, 32, 4, false, false><<<blocks_for(nw, T), T>>>(csr, rp, A, dinv, nullptr, B, n);
    k_dense<32, 64, 32, 64, true, true, true><<<blocks_for(n, 128), 128>>>(B, W2, b2, dinv, A, n);

    // L3: y3 = agg(z2) -> B ; h3 = relu(y3 W3 + b3) -> A (64)
    k_gather<64, 64, 4, false, false><<<blocks_for(nw, T), T>>>(csr, rp, A, dinv, nullptr, B, n);
    k_dense<64, 64, 64, 64, true, true, false><<<blocks_for(n, 128), 128>>>(B, W3, b3, dinv, A, n);

    // L4: z4 = dinv*(h3 W4) -> B (32) ; h4 = relu(agg(z4)+b4) -> A (32)
    k_dense<64, 32, 64, 32, false, false, true><<<blocks_for(n, 128), 128>>>(A, W4, nullptr, dinv, B, n);
    k_gather<32, 32, 4, true, true><<<blocks_for(nw, T), T>>>(csr, rp, B, dinv, b4, A, n);

    // L5: z5 = dinv*(h4 W5) -> B (stride 4, pad 0) ; out = agg(z5)+b5
    k_dense<32, 3, 32, 4, false, false, true><<<blocks_for(n, 128), 128>>>(A, W5, nullptr, dinv, B, n);
    k_gather<4, 3, 2, true, false><<<blocks_for(nw, T), T>>>(csr, rp, B, dinv, b5, out, n);
}

// round 9
// speedup vs baseline: 1.2353x; 1.1386x over previous
#include <cuda_runtime.h>
#include <cstdint>

// ---------------------------------------------------------------------------
// SimpleGNNDenoiser: 5-layer GCN, N=100k, E=3.2M.
//   Â(XW) = (ÂX)W ; z-trick: producers store z = dinv*h so aggregation is
//   y_i = dinv_i * (sum_{s in N(i)} z_s + z_i)  -- no per-edge weights.
// R9: predicated gather loads (masked slots skip the LDG), dense3+dense4
//     fused in one register-resident kernel, dense5 fused into the L4
//     gather epilogue. 9 kernels total.
// ---------------------------------------------------------------------------

#define N_MAX 100000
#define E_MAX 3200000
#define SCAN_B 1024

static __device__ float g_bufA[N_MAX * 64];
static __device__ float g_bufB[N_MAX * 64];
static __device__ float4 g_pack[N_MAX];              // [dinv*cx, dinv*cy, dinv*cz, +-dinv]
static __device__ float g_dinv[N_MAX];
static __device__ int   g_csr[E_MAX];
static __device__ int   g_rp[N_MAX + 1];
static __device__ int   g_cnt[N_MAX];
static __device__ int   g_cur[N_MAX];
static __device__ unsigned long long g_state[128];   // lookback: (status<<32)|sum

// ---- CSR build ---------------------------------------------------------------

__global__ void k_hist(const int* __restrict__ dst, int* cnt, int E) {
    int e = blockIdx.x * blockDim.x + threadIdx.x;
    if (e < E) atomicAdd(&cnt[dst[e]], 1);
}

// Single-pass decoupled-lookback exclusive scan; emits rp, cur, dinv and the
// dinv-scaled packed features. 98 blocks co-resident -> lookback can't deadlock.
__global__ void __launch_bounds__(SCAN_B)
k_scan_lb(const int* __restrict__ cnt, unsigned long long* __restrict__ state,
          int* __restrict__ rp, int* __restrict__ cur, float* __restrict__ dinv,
          const float* __restrict__ coords, const int* __restrict__ types,
          float4* __restrict__ pack, int n) {
    __shared__ int s[SCAN_B];
    __shared__ int sbase;
    int t = threadIdx.x;
    int bid = blockIdx.x;
    int i = bid * SCAN_B + t;
    int v = (i < n) ? cnt[i] : 0;
    s[t] = v;
    __syncthreads();
    for (int off = 1; off < SCAN_B; off <<= 1) {
        int u = (t >= off) ? s[t - off] : 0;
        __syncthreads();
        s[t] += u;
        __syncthreads();
    }
    int total = s[SCAN_B - 1];

    if (t == 0) {
        if (bid == 0) {
            atomicExch(&state[0], (2ULL << 32) | (unsigned)total);
            sbase = 0;
        } else {
            atomicExch(&state[bid], (1ULL << 32) | (unsigned)total);
            int run = 0;
            int p = bid - 1;
            while (p >= 0) {
                unsigned long long w;
                do { w = atomicAdd(&state[p], 0ULL); } while ((w >> 32) == 0ULL);
                run += (int)(w & 0xffffffffULL);
                if ((w >> 32) == 2ULL) break;
                p--;
            }
            atomicExch(&state[bid], (2ULL << 32) | (unsigned)(run + total));
            sbase = run;
        }
    }
    __syncthreads();
    if (i < n) {
        int excl = sbase + s[t] - v;
        rp[i] = excl;
        cur[i] = excl;
        float dv = rsqrtf(1.0f + (float)v);
        dinv[i] = dv;
        if (i == n - 1) rp[n] = excl + v;
        float4 p;
        p.x = dv * coords[3 * (size_t)i + 0];
        p.y = dv * coords[3 * (size_t)i + 1];
        p.z = dv * coords[3 * (size_t)i + 2];
        p.w = (types[i] == 0) ? dv : -dv;
        pack[i] = p;
    }
}

__global__ void k_fill(const int* __restrict__ src, const int* __restrict__ dst,
                       int* __restrict__ cur, int* __restrict__ csr, int E) {
    int e = blockIdx.x * blockDim.x + threadIdx.x;
    if (e >= E) return;
    int d = dst[e];
    int pos = atomicAdd(&cur[d], 1);
    csr[pos] = src[e];
}

// ---- K1: fused packed gather + dense1(6->32) + bias + relu; writes z1 --------

__global__ void __launch_bounds__(256)
k_l1_fused(const int* __restrict__ csr, const int* __restrict__ rp,
           const float4* __restrict__ pack, const float* __restrict__ emb,
           const float* __restrict__ dinv, const float* __restrict__ W1,
           const float* __restrict__ b1, float* __restrict__ out, int n) {
    int warp = (blockIdx.x * blockDim.x + threadIdx.x) >> 5;
    if (warp >= n) return;
    int lane = threadIdx.x & 31;
    int i = warp;
    int beg = rp[i], end = rp[i + 1];

    float ax = 0.f, ay = 0.f, az = 0.f, m0 = 0.f, m1 = 0.f;
    for (int idx = beg + lane; idx < end; idx += 32) {
        float4 p = pack[csr[idx]];
        ax += p.x; ay += p.y; az += p.z;
        m0 += fmaxf(p.w, 0.f);
        m1 += fmaxf(-p.w, 0.f);
    }
#pragma unroll
    for (int off = 1; off < 32; off <<= 1) {
        ax += __shfl_xor_sync(0xffffffffu, ax, off);
        ay += __shfl_xor_sync(0xffffffffu, ay, off);
        az += __shfl_xor_sync(0xffffffffu, az, off);
        m0 += __shfl_xor_sync(0xffffffffu, m0, off);
        m1 += __shfl_xor_sync(0xffffffffu, m1, off);
    }
    float dv = dinv[i];
    float4 ps = pack[i];                 // self term (z row)
    ax = dv * (ax + ps.x);
    ay = dv * (ay + ps.y);
    az = dv * (az + ps.z);
    m0 = dv * (m0 + fmaxf(ps.w, 0.f));
    m1 = dv * (m1 + fmaxf(-ps.w, 0.f));

    float x3 = fmaf(m0, emb[0], m1 * emb[3]);
    float x4 = fmaf(m0, emb[1], m1 * emb[4]);
    float x5 = fmaf(m0, emb[2], m1 * emb[5]);

    float acc = b1[lane];
    acc = fmaf(ax, W1[0 * 32 + lane], acc);
    acc = fmaf(ay, W1[1 * 32 + lane], acc);
    acc = fmaf(az, W1[2 * 32 + lane], acc);
    acc = fmaf(x3, W1[3 * 32 + lane], acc);
    acc = fmaf(x4, W1[4 * 32 + lane], acc);
    acc = fmaf(x5, W1[5 * 32 + lane], acc);
    out[(size_t)i * 32 + lane] = dv * fmaxf(acc, 0.f);   // z1 = dinv * h1
}

// ---- gather core (predicated): returns warp-reduced float4 for lanes < SL ---
// Masked slots issue NO load (saves L1tex wavefronts).

template<int W, int U>
__device__ __forceinline__ float4 gather_acc(
    const int* __restrict__ csr, const int* __restrict__ rp,
    const float4* __restrict__ x4, int i, int lane) {
    constexpr int SL = W / 4;
    constexpr int NB = 32 / SL;
    int nb = lane / SL;
    int c4 = lane & (SL - 1);
    int beg = rp[i], end = rp[i + 1];

    float4 a[U];
#pragma unroll
    for (int u = 0; u < U; u++) a[u] = make_float4(0.f, 0.f, 0.f, 0.f);

    for (int base = beg + nb; base < end; base += U * NB) {
#pragma unroll
        for (int u = 0; u < U; u++) {
            int id = base + u * NB;
            if (id < end) {
                int srcn = csr[id];
                float4 v = x4[(size_t)srcn * SL + c4];
                a[u].x += v.x; a[u].y += v.y; a[u].z += v.z; a[u].w += v.w;
            }
        }
    }

    float4 acc = a[0];
#pragma unroll
    for (int u = 1; u < U; u++) {
        acc.x += a[u].x; acc.y += a[u].y; acc.z += a[u].z; acc.w += a[u].w;
    }
#pragma unroll
    for (int off = SL; off < 32; off <<= 1) {
        acc.x += __shfl_xor_sync(0xffffffffu, acc.x, off);
        acc.y += __shfl_xor_sync(0xffffffffu, acc.y, off);
        acc.z += __shfl_xor_sync(0xffffffffu, acc.z, off);
        acc.w += __shfl_xor_sync(0xffffffffu, acc.w, off);
    }
    return acc;
}

// ---- generic gather kernel: y = dinv_i*(acc + z_i), optional bias/relu ------

template<int W, int OUTW, int U, bool BIAS, bool RELU>
__global__ void __launch_bounds__(256)
k_gather(const int* __restrict__ csr, const int* __restrict__ rp,
         const float* __restrict__ x, const float* __restrict__ dinv,
         const float* __restrict__ b, float* __restrict__ y, int n) {
    constexpr int SL = W / 4;
    int warp = (blockIdx.x * blockDim.x + threadIdx.x) >> 5;
    if (warp >= n) return;
    int lane = threadIdx.x & 31;
    int c4 = lane & (SL - 1);
    int i = warp;
    const float4* x4 = reinterpret_cast<const float4*>(x);

    float4 acc = gather_acc<W, U>(csr, rp, x4, i, lane);

    if (lane < SL) {
        float dv = dinv[i];
        float4 xs = x4[(size_t)i * SL + c4];     // self z row
        float4 r;
        r.x = dv * (acc.x + xs.x);
        r.y = dv * (acc.y + xs.y);
        r.z = dv * (acc.z + xs.z);
        r.w = dv * (acc.w + xs.w);
        int col = c4 * 4;
        if (BIAS) {
            if (col + 0 < OUTW) r.x += b[col + 0];
            if (col + 1 < OUTW) r.y += b[col + 1];
            if (col + 2 < OUTW) r.z += b[col + 2];
            if (col + 3 < OUTW) r.w += b[col + 3];
        }
        if (RELU) {
            r.x = fmaxf(r.x, 0.f); r.y = fmaxf(r.y, 0.f);
            r.z = fmaxf(r.z, 0.f); r.w = fmaxf(r.w, 0.f);
        }
        if constexpr (OUTW % 4 == 0) {
            reinterpret_cast<float4*>(y + (size_t)i * OUTW)[c4] = r;
        } else {                    // OUTW==3 (final layer), SL==1
            float* yr = y + (size_t)i * OUTW;
            yr[0] = r.x; yr[1] = r.y; yr[2] = r.z;
        }
    }
}

// ---- K_L4: gather@32 + b4 + relu + dense5(32->3) -> z5 (stride 4) -----------
// Lanes < 8 hold 4 cols of h4 each; partial dot with W5, butterfly over the
// 8-lane group, lane 0 writes z5 = dinv * (h4 W5).

__global__ void __launch_bounds__(256)
k_l4(const int* __restrict__ csr, const int* __restrict__ rp,
     const float* __restrict__ x, const float* __restrict__ dinv,
     const float* __restrict__ b4, const float* __restrict__ W5,
     float* __restrict__ y, int n) {
    int warp = (blockIdx.x * blockDim.x + threadIdx.x) >> 5;
    if (warp >= n) return;
    int lane = threadIdx.x & 31;
    int c4 = lane & 7;
    int i = warp;
    const float4* x4 = reinterpret_cast<const float4*>(x);

    float4 acc = gather_acc<32, 4>(csr, rp, x4, i, lane);

    float dv = dinv[i];
    float p0 = 0.f, p1 = 0.f, p2 = 0.f;
    if (lane < 8) {
        float4 xs = x4[(size_t)i * 8 + c4];
        int col = c4 * 4;
        float h0 = fmaxf(dv * (acc.x + xs.x) + b4[col + 0], 0.f);
        float h1 = fmaxf(dv * (acc.y + xs.y) + b4[col + 1], 0.f);
        float h2 = fmaxf(dv * (acc.z + xs.z) + b4[col + 2], 0.f);
        float h3 = fmaxf(dv * (acc.w + xs.w) + b4[col + 3], 0.f);
        p0 = h0 * W5[(col + 0) * 3 + 0] + h1 * W5[(col + 1) * 3 + 0]
           + h2 * W5[(col + 2) * 3 + 0] + h3 * W5[(col + 3) * 3 + 0];
        p1 = h0 * W5[(col + 0) * 3 + 1] + h1 * W5[(col + 1) * 3 + 1]
           + h2 * W5[(col + 2) * 3 + 1] + h3 * W5[(col + 3) * 3 + 1];
        p2 = h0 * W5[(col + 0) * 3 + 2] + h1 * W5[(col + 1) * 3 + 2]
           + h2 * W5[(col + 2) * 3 + 2] + h3 * W5[(col + 3) * 3 + 2];
    }
#pragma unroll
    for (int off = 1; off < 8; off <<= 1) {
        p0 += __shfl_xor_sync(0xffffffffu, p0, off);
        p1 += __shfl_xor_sync(0xffffffffu, p1, off);
        p2 += __shfl_xor_sync(0xffffffffu, p2, off);
    }
    if (lane == 0) {
        float4 r = make_float4(dv * p0, dv * p1, dv * p2, 0.f);
        reinterpret_cast<float4*>(y)[i] = r;          // z5 (stride 4)
    }
}

// ---- K2 dense: z2 = dinv * relu(y2 W2 + b2), 32 -> 64 -----------------------

__global__ void __launch_bounds__(128)
k_d2(const float* __restrict__ x, const float* __restrict__ W2,
     const float* __restrict__ b2, const float* __restrict__ dinv,
     float* __restrict__ out, int n) {
    __shared__ float Ws[32 * 64];
    __shared__ float bs[64];
    for (int t = threadIdx.x; t < 32 * 64; t += 128) Ws[t] = W2[t];
    for (int t = threadIdx.x; t < 64; t += 128) bs[t] = b2[t];
    __syncthreads();
    int i = blockIdx.x * blockDim.x + threadIdx.x;
    if (i >= n) return;
    float acc[64];
#pragma unroll
    for (int j = 0; j < 64; j++) acc[j] = bs[j];
    const float4* x4 = reinterpret_cast<const float4*>(x + (size_t)i * 32);
#pragma unroll
    for (int k4 = 0; k4 < 8; k4++) {
        float4 xv = x4[k4];
        int k = k4 * 4;
#pragma unroll
        for (int j = 0; j < 64; j++) {
            acc[j] = fmaf(xv.x, Ws[(k + 0) * 64 + j], acc[j]);
            acc[j] = fmaf(xv.y, Ws[(k + 1) * 64 + j], acc[j]);
            acc[j] = fmaf(xv.z, Ws[(k + 2) * 64 + j], acc[j]);
            acc[j] = fmaf(xv.w, Ws[(k + 3) * 64 + j], acc[j]);
        }
    }
    float dv = dinv[i];
    float* o = out + (size_t)i * 64;
#pragma unroll
    for (int j = 0; j < 64; j++) o[j] = dv * fmaxf(acc[j], 0.0f);
}

// ---- K_D34: z4 = dinv * ( relu(y3 W3 + b3) W4 ), 64 -> 64 -> 32 -------------
// W3 staged TRANSPOSED in smem (k consecutive per j -> LDS.128), W4 native.
// h3 streams one element at a time; never materialized.

__global__ void __launch_bounds__(128)
k_d34(const float* __restrict__ x, const float* __restrict__ W3,
      const float* __restrict__ b3, const float* __restrict__ W4,
      const float* __restrict__ dinv, float* __restrict__ out, int n) {
    __shared__ float W3t[64 * 64];   // W3t[j*64 + k] = W3[k*64 + j]
    __shared__ float W4s[64 * 32];
    __shared__ float bs[64];
    for (int t = threadIdx.x; t < 64 * 64; t += 128) {
        int k = t >> 6, j = t & 63;
        W3t[j * 64 + k] = W3[t];
    }
    for (int t = threadIdx.x; t < 64 * 32; t += 128) W4s[t] = W4[t];
    for (int t = threadIdx.x; t < 64; t += 128) bs[t] = b3[t];
    __syncthreads();

    int i = blockIdx.x * blockDim.x + threadIdx.x;
    if (i >= n) return;

    float4 xv[16];
    const float4* x4 = reinterpret_cast<const float4*>(x + (size_t)i * 64);
#pragma unroll
    for (int k4 = 0; k4 < 16; k4++) xv[k4] = x4[k4];

    float acc[32];
#pragma unroll
    for (int j = 0; j < 32; j++) acc[j] = 0.f;

#pragma unroll 4
    for (int j = 0; j < 64; j++) {
        float h = bs[j];
        const float4* w3r = reinterpret_cast<const float4*>(&W3t[j * 64]);
#pragma unroll
        for (int k4 = 0; k4 < 16; k4++) {
            float4 w = w3r[k4];
            h = fmaf(xv[k4].x, w.x, h);
            h = fmaf(xv[k4].y, w.y, h);
            h = fmaf(xv[k4].z, w.z, h);
            h = fmaf(xv[k4].w, w.w, h);
        }
        h = fmaxf(h, 0.f);
        const float4* w4r = reinterpret_cast<const float4*>(&W4s[j * 32]);
#pragma unroll
        for (int j4 = 0; j4 < 8; j4++) {
            float4 w = w4r[j4];
            acc[j4 * 4 + 0] = fmaf(h, w.x, acc[j4 * 4 + 0]);
            acc[j4 * 4 + 1] = fmaf(h, w.y, acc[j4 * 4 + 1]);
            acc[j4 * 4 + 2] = fmaf(h, w.z, acc[j4 * 4 + 2]);
            acc[j4 * 4 + 3] = fmaf(h, w.w, acc[j4 * 4 + 3]);
        }
    }
    float dv = dinv[i];
    float* o = out + (size_t)i * 32;
#pragma unroll
    for (int j = 0; j < 32; j++) o[j] = dv * acc[j];
}

// ---------------------------------------------------------------------------

static inline int blocks_for(long long work, int tpb) {
    return (int)((work + tpb - 1) / tpb);
}

extern "C" void kernel_launch(void* const* d_in, const int* in_sizes, int n_in,
                              void* d_out, int out_size) {
    const float* coords = (const float*)d_in[0];
    const int*   types  = (const int*)d_in[1];
    const int*   edge   = (const int*)d_in[2];
    const float* emb    = (const float*)d_in[3];
    const float* W1 = (const float*)d_in[4];
    const float* b1 = (const float*)d_in[5];
    const float* W2 = (const float*)d_in[6];
    const float* b2 = (const float*)d_in[7];
    const float* W3 = (const float*)d_in[8];
    const float* b3 = (const float*)d_in[9];
    const float* W4 = (const float*)d_in[10];
    const float* b4 = (const float*)d_in[11];
    const float* W5 = (const float*)d_in[12];
    const float* b5 = (const float*)d_in[13];
    float* out = (float*)d_out;

    const int n = in_sizes[0] / 3;
    const int E = in_sizes[2] / 2;
    const int* src = edge;
    const int* dst = edge + E;

    float *A, *B, *dinv;
    float4* pack;
    int *csr, *rp, *cnt, *cur;
    unsigned long long* state;
    cudaGetSymbolAddress((void**)&A, g_bufA);
    cudaGetSymbolAddress((void**)&B, g_bufB);
    cudaGetSymbolAddress((void**)&pack, g_pack);
    cudaGetSymbolAddress((void**)&dinv, g_dinv);
    cudaGetSymbolAddress((void**)&csr, g_csr);
    cudaGetSymbolAddress((void**)&rp, g_rp);
    cudaGetSymbolAddress((void**)&cnt, g_cnt);
    cudaGetSymbolAddress((void**)&cur, g_cur);
    cudaGetSymbolAddress((void**)&state, g_state);

    const int T = 256;
    const long long nw = (long long)n * 32;   // one warp per node
    const int PB = blocks_for(n, SCAN_B);     // 98 scan blocks

    cudaMemsetAsync(cnt, 0, (size_t)n * sizeof(int));
    cudaMemsetAsync(state, 0, 128 * sizeof(unsigned long long));

    // ---- CSR build + packed z-features ----
    k_hist<<<blocks_for(E, T), T>>>(dst, cnt, E);                                 // 1
    k_scan_lb<<<PB, SCAN_B>>>(cnt, state, rp, cur, dinv, coords, types, pack, n); // 2
    k_fill<<<blocks_for(E, T), T>>>(src, dst, cur, csr, E);                       // 3

    // K1: L1 fused -> z1 in A (stride 32)                   [launch 4: profiled]
    k_l1_fused<<<blocks_for(nw, T), T>>>(csr, rp, pack, emb, dinv, W1, b1, A, n);

    // L2: y2 = agg(z1) -> B ; z2 = dinv*relu(y2 W2 + b2) -> A (64)
    k_gather<32, 32, 4, false, false><<<blocks_for(nw, T), T>>>(csr, rp, A, dinv, nullptr, B, n);
    k_d2<<<blocks_for(n, 128), 128>>>(B, W2, b2, dinv, A, n);

    // L3: y3 = agg(z2) -> B ; z4 = dinv*(relu(y3 W3 + b3) W4) -> A (32)
    k_gather<64, 64, 4, false, false><<<blocks_for(nw, T), T>>>(csr, rp, A, dinv, nullptr, B, n);
    k_d34<<<blocks_for(n, 128), 128>>>(B, W3, b3, W4, dinv, A, n);

    // L4+L5-dense: h4 = relu(agg(z4)+b4); z5 = dinv*(h4 W5) -> B (stride 4)
    k_l4<<<blocks_for(nw, T), T>>>(csr, rp, A, dinv, b4, W5, B, n);

    // final: out = agg(z5) + b5
    k_gather<4, 3, 2, true, false><<<blocks_for(nw, T), T>>>(csr, rp, B, dinv, b5, out, n);
}